// round 16
// baseline (speedup 1.0000x reference)
#include <cuda_runtime.h>
#include <cuda_bf16.h>
#include <math.h>
#include <stdint.h>

#define BB   32
#define HH   40
#define WW   256
#define FREQ 40
#define C0   32
#define H0   38
#define C1   64
#define H1   36
#define W1   252
#define K_FC (C1*H1*W1)          /* 580608 */
#define NCHUNK 148               /* fc blocks; 4536 k128-tiles split 31/30 */
#define TWO_PI 6.28318530717958647692f

/* ---------------- scratch (device globals) ------------------------------- */
__device__ __nv_bfloat16 g_x1h[(size_t)BB*K_FC];      /* conv1 out, bf16   */
__device__ float         g_feats[BB*HH*WW];
__device__ float2        g_trig[FREQ*WW];             /* (sin, cos) pairs  */
__device__ float         g_gpart[(size_t)FREQ*BB*NCHUNK];  /* [p][chunk] */
__device__ float         g_gates[BB*FREQ];

/* ---------------- helpers ------------------------------------------------- */
__device__ __forceinline__ uint32_t packbf2(float lo, float hi) {
    __nv_bfloat162 h = __floats2bfloat162_rn(lo, hi);
    return *(uint32_t*)&h;
}

__device__ __forceinline__ void mma_bf16(float c[4], const uint32_t a[4],
                                         const uint32_t b[2]) {
    asm volatile(
        "mma.sync.aligned.m16n8k16.row.col.f32.bf16.bf16.f32 "
        "{%0,%1,%2,%3}, {%4,%5,%6,%7}, {%8,%9}, {%0,%1,%2,%3};"
        : "+f"(c[0]), "+f"(c[1]), "+f"(c[2]), "+f"(c[3])
        : "r"(a[0]), "r"(a[1]), "r"(a[2]), "r"(a[3]), "r"(b[0]), "r"(b[1]));
}

/* ---------------- conv1_mega: conv0 fused, persistent, double-buffered ----
 * Grid 148 CTAs x 512 thr; tiles (i2, b), tile = bid + k*148, 576 total.
 * conv0: R13 flat thread map (warp streams contiguous rows — proven fastest).
 * Warp = rsel(2) x nhalf(2) x mblk(4); 64j x 32oc tile, 16 MMA per k16. */
#define XR    258
#define BUFU  (64*XR)                       /* 16512 u32 */
#define SM1   ((2*BUFU + 2304*4)*4)         /* 168960 bytes */

__device__ __forceinline__ void conv0_tile(uint32_t* dst,
                                           const float* __restrict__ in,
                                           const float* __restrict__ w0,
                                           const float* __restrict__ b0,
                                           int tile, int tid) {
    int i2t = tile % 18, bt = tile / 18;
    const float* ip = in + (size_t)bt*HH*WW;
    for (int idx = tid; idx < 4096; idx += 512) {
        int jg = idx & 63;          /* 64 groups of 4 cols */
        int t2 = idx >> 6;
        int dr = t2 & 3;
        int op = t2 >> 2;           /* icp 0..15 */
        int j0 = jg*4;
        int oc0 = op*2;
        int ir  = 2*i2t + dr;       /* x0 row, <= 37 */

        float wA[9], wB[9];
#pragma unroll
        for (int q = 0; q < 9; q++) {
            wA[q] = __ldg(&w0[oc0*9+q]);
            wB[q] = __ldg(&w0[oc0*9+9+q]);
        }
        float biasA = __ldg(&b0[oc0]);
        float biasB = __ldg(&b0[oc0+1]);
        float aA[4] = {biasA, biasA, biasA, biasA};
        float aB[4] = {biasB, biasB, biasB, biasB};

#pragma unroll
        for (int di = 0; di < 3; di++) {
            const float* row = ip + (ir+di)*WW;
            float x[6];
#pragma unroll
            for (int c = 0; c < 6; c++) x[c] = (j0+c < WW) ? row[j0+c] : 0.0f;
#pragma unroll
            for (int dj = 0; dj < 3; dj++) {
                float wa = wA[di*3+dj], wb = wB[di*3+dj];
#pragma unroll
                for (int q = 0; q < 4; q++) {
                    aA[q] += wa * x[q+dj];
                    aB[q] += wb * x[q+dj];
                }
            }
        }
        uint32_t v[4];
#pragma unroll
        for (int q = 0; q < 4; q++) {
            bool ok = (j0+q < 254);
            v[q] = packbf2(ok ? fmaxf(aA[q], 0.0f) : 0.0f,
                           ok ? fmaxf(aB[q], 0.0f) : 0.0f);
        }
        uint32_t* o = dst + (op*4 + dr)*XR + j0;
        *(uint2*)(o)     = make_uint2(v[0], v[1]);
        *(uint2*)(o + 2) = make_uint2(v[2], v[3]);
    }
}

__global__ void __launch_bounds__(512)
conv1_mega(const float* __restrict__ in,
           const float* __restrict__ w0,
           const float* __restrict__ b0,
           const float* __restrict__ w1,
           const float* __restrict__ b1) {
    extern __shared__ uint32_t smem[];
    uint4* wsm = (uint4*)(smem + 2*BUFU);

    int tid = threadIdx.x;
    int bid = blockIdx.x;

    /* build conv1 weight fragments in-CTA ([t9][kh][nq][lane] -> uint4) */
    for (int t = tid; t < 2304; t += 512) {
        int lane = t & 31;
        int nq   = (t >> 5) & 3;
        int kh   = (t >> 7) & 1;
        int t9   = t >> 8;
        int gid = lane >> 2, tig = lane & 3;
        int ic0 = 2*tig + 16*kh;
        int oc0 = nq*16 + gid;
        int oc1 = oc0 + 8;
        uint4 v;
        v.x = packbf2(__ldg(&w1[oc0*288 + (ic0  )*9 + t9]),
                      __ldg(&w1[oc0*288 + (ic0+1)*9 + t9]));
        v.y = packbf2(__ldg(&w1[oc0*288 + (ic0+8)*9 + t9]),
                      __ldg(&w1[oc0*288 + (ic0+9)*9 + t9]));
        v.z = packbf2(__ldg(&w1[oc1*288 + (ic0  )*9 + t9]),
                      __ldg(&w1[oc1*288 + (ic0+1)*9 + t9]));
        v.w = packbf2(__ldg(&w1[oc1*288 + (ic0+8)*9 + t9]),
                      __ldg(&w1[oc1*288 + (ic0+9)*9 + t9]));
        wsm[t] = v;
    }
    /* zero pad cols 256..257 of both buffers */
    if (tid < 256) {
        int bsel = tid >> 7, rr = (tid >> 1) & 63, c = tid & 1;
        smem[bsel*BUFU + rr*XR + 256 + c] = 0u;
    }

    int ntiles = (bid < 132) ? 4 : 3;

    conv0_tile(smem, in, w0, b0, bid, tid);   /* tile 0 -> buf0 */
    __syncthreads();

    int warp  = tid >> 5;
    int lane  = tid & 31;
    int mblk  = warp & 3;
    int nhalf = (warp >> 2) & 1;
    int rsel  = warp >> 3;
    int gid   = lane >> 2;
    int tig   = lane & 3;

    for (int k = 0; k < ntiles; k++) {
        if (k + 1 < ntiles)
            conv0_tile(smem + ((k+1)&1)*BUFU, in, w0, b0, bid + (k+1)*148, tid);
        __syncthreads();

        const uint32_t* xsp = smem + (k&1)*BUFU;
        int tile = bid + k*148;
        int i2t = tile % 18, bt = tile / 18;

        float cacc[4][4][4];
#pragma unroll
        for (int mf = 0; mf < 4; mf++)
#pragma unroll
            for (int nf = 0; nf < 4; nf++)
#pragma unroll
                for (int q = 0; q < 4; q++) cacc[mf][nf][q] = 0.0f;

#pragma unroll
        for (int t9 = 0; t9 < 9; t9++) {
            int di = t9 / 3, dj = t9 % 3;
            int dr = di + rsel;
#pragma unroll
            for (int kh = 0; kh < 2; kh++) {
                uint4 wv0 = wsm[((t9*2 + kh)*4 + 2*nhalf    )*32 + lane];
                uint4 wv1 = wsm[((t9*2 + kh)*4 + 2*nhalf + 1)*32 + lane];
                uint32_t bfrag[4][2];
                bfrag[0][0] = wv0.x; bfrag[0][1] = wv0.y;
                bfrag[1][0] = wv0.z; bfrag[1][1] = wv0.w;
                bfrag[2][0] = wv1.x; bfrag[2][1] = wv1.y;
                bfrag[3][0] = wv1.z; bfrag[3][1] = wv1.w;
                const uint32_t* xa = xsp + ((kh*8 + tig    )*4 + dr)*XR + dj;
                const uint32_t* xb = xsp + ((kh*8 + tig + 4)*4 + dr)*XR + dj;
#pragma unroll
                for (int mf = 0; mf < 4; mf++) {
                    int j0 = mblk*64 + mf*16 + gid;
                    uint32_t afrag[4];
                    afrag[0] = xa[j0];
                    afrag[1] = xa[j0 + 8];
                    afrag[2] = xb[j0];
                    afrag[3] = xb[j0 + 8];
#pragma unroll
                    for (int nf = 0; nf < 4; nf++)
                        mma_bf16(cacc[mf][nf], afrag, bfrag[nf]);
                }
            }
        }

        /* epilogue: bias + relu + bf16 store to g_x1h[b][oc][i][j] */
        int i = 2*i2t + rsel;
#pragma unroll
        for (int nf = 0; nf < 4; nf++) {
            int oc = nhalf*32 + nf*8 + tig*2;
            float bias0 = __ldg(&b1[oc]);
            float bias1 = __ldg(&b1[oc+1]);
            __nv_bfloat16* o0 = g_x1h + (size_t)bt*K_FC +
                                (size_t)oc*(H1*W1) + (size_t)i*W1;
            __nv_bfloat16* o1 = o0 + H1*W1;
#pragma unroll
            for (int mf = 0; mf < 4; mf++) {
                int j = mblk*64 + mf*16 + gid;
                if (j < W1) {
                    o0[j] = __float2bfloat16_rn(fmaxf(cacc[mf][nf][0] + bias0, 0.0f));
                    o1[j] = __float2bfloat16_rn(fmaxf(cacc[mf][nf][1] + bias1, 0.0f));
                }
                if (j + 8 < W1) {
                    o0[j+8] = __float2bfloat16_rn(fmaxf(cacc[mf][nf][2] + bias0, 0.0f));
                    o1[j+8] = __float2bfloat16_rn(fmaxf(cacc[mf][nf][3] + bias1, 0.0f));
                }
            }
        }
        __syncthreads();
    }
}

/* ---------------- fc_plus: fc GEMM + feats + trig in one launch ----------
 * blocks [0,148): fc (register prefetch, 31/30 tiles);
 * blocks [148,1428): feats (independent of fc — fills idle SM capacity);
 * blocks [1428,1468): trig tables. */
__global__ void __launch_bounds__(256) fc_plus(const float* __restrict__ wr,
                                               const float* __restrict__ in,
                                               const float* __restrict__ wf,
                                               const float* __restrict__ bf) {
    int bid = blockIdx.x;
    int tid = threadIdx.x;

    if (bid >= 148) {
        if (bid < 1428) {
            /* feats: 5-tap conv along W, zero pad, + bias */
            int idx = (bid - 148)*256 + tid;
            int w = idx & (WW-1);
            const float* row = in + (idx - w);
            float acc = __ldg(&bf[0]);
#pragma unroll
            for (int t = 0; t < 5; t++) {
                int ww = w + t - 2;
                if (ww >= 0 && ww < WW) acc += __ldg(&wf[t]) * row[ww];
            }
            g_feats[idx] = acc;
        } else {
            /* trig tables (sin, cos interleaved) */
            int f = bid - 1428;
            int w = tid;
            float fs = 2.0f * (float)(f+1);
            float t  = (0.5f/255.0f) * (float)w;
            float ph = TWO_PI * fs * t;
            float sv, cv;
            sincosf(ph, &sv, &cv);
            g_trig[f*WW + w] = make_float2(sv, cv);
        }
        return;
    }

    __shared__ union {
        struct { uint32_t wrs[48*68]; uint32_t x1s[32*68]; } t;
        float red[8*FREQ*BB];
    } sm;
    int chunk = bid;
    int warp  = tid >> 5;
    int lane  = tid & 31;
    int gid   = lane >> 2;
    int tig   = lane & 3;

    int tile0 = chunk*30 + ((chunk < 96) ? chunk : 96);
    int nt    = 30 + ((chunk < 96) ? 1 : 0);

    for (int s = tid; s < 8*68; s += 256) sm.t.wrs[40*68 + s] = 0u;

    float acc[3][4][4];
#pragma unroll
    for (int mt = 0; mt < 3; mt++)
#pragma unroll
        for (int nt2 = 0; nt2 < 4; nt2++)
#pragma unroll
            for (int q = 0; q < 4; q++) acc[mt][nt2][q] = 0.0f;

    const float4* wr4 = (const float4*)wr;
    float4 wbuf[5];
    uint4  xbuf[2];

    {
        int k0 = tile0*128;
#pragma unroll
        for (int s = 0; s < 5; s++) {
            int idx = tid + s*256;
            int r = idx >> 5, cc = idx & 31;
            wbuf[s] = wr4[(size_t)r*(K_FC/4) + (k0 >> 2) + cc];
        }
#pragma unroll
        for (int s = 0; s < 2; s++) {
            int idx = tid + s*256;
            int r = idx >> 4, cc = idx & 15;
            xbuf[s] = *(const uint4*)(g_x1h + (size_t)r*K_FC + k0 + cc*8);
        }
    }

    for (int tile = 0; tile < nt; tile++) {
#pragma unroll
        for (int s = 0; s < 5; s++) {
            int idx = tid + s*256;
            int r = idx >> 5, cc = idx & 31;
            sm.t.wrs[r*68 + 2*cc]     = packbf2(wbuf[s].x, wbuf[s].y);
            sm.t.wrs[r*68 + 2*cc + 1] = packbf2(wbuf[s].z, wbuf[s].w);
        }
#pragma unroll
        for (int s = 0; s < 2; s++) {
            int idx = tid + s*256;
            int r = idx >> 4, cc = idx & 15;
            *(uint4*)&sm.t.x1s[r*68 + cc*4] = xbuf[s];
        }
        __syncthreads();

        if (tile + 1 < nt) {
            int k0 = (tile0 + tile + 1)*128;
#pragma unroll
            for (int s = 0; s < 5; s++) {
                int idx = tid + s*256;
                int r = idx >> 5, cc = idx & 31;
                wbuf[s] = wr4[(size_t)r*(K_FC/4) + (k0 >> 2) + cc];
            }
#pragma unroll
            for (int s = 0; s < 2; s++) {
                int idx = tid + s*256;
                int r = idx >> 4, cc = idx & 15;
                xbuf[s] = *(const uint4*)(g_x1h + (size_t)r*K_FC + k0 + cc*8);
            }
        }

        int ko = warp*8 + tig;
        uint32_t bfrag[4][2];
#pragma unroll
        for (int nt2 = 0; nt2 < 4; nt2++) {
            bfrag[nt2][0] = sm.t.x1s[(nt2*8 + gid)*68 + ko];
            bfrag[nt2][1] = sm.t.x1s[(nt2*8 + gid)*68 + ko + 4];
        }
#pragma unroll
        for (int mt = 0; mt < 3; mt++) {
            uint32_t afrag[4];
            afrag[0] = sm.t.wrs[(mt*16 + gid    )*68 + ko];
            afrag[1] = sm.t.wrs[(mt*16 + gid + 8)*68 + ko];
            afrag[2] = sm.t.wrs[(mt*16 + gid    )*68 + ko + 4];
            afrag[3] = sm.t.wrs[(mt*16 + gid + 8)*68 + ko + 4];
#pragma unroll
            for (int nt2 = 0; nt2 < 4; nt2++)
                mma_bf16(acc[mt][nt2], afrag, bfrag[nt2]);
        }
        __syncthreads();
    }

#pragma unroll
    for (int mt = 0; mt < 3; mt++)
#pragma unroll
        for (int nt2 = 0; nt2 < 4; nt2++) {
            int f0 = mt*16 + gid;
            int b0 = nt2*8 + 2*tig;
            float* rp = sm.red + warp*(FREQ*BB);
            if (f0 < FREQ) {
                rp[f0*BB + b0]     = acc[mt][nt2][0];
                rp[f0*BB + b0 + 1] = acc[mt][nt2][1];
            }
            if (f0 + 8 < FREQ) {
                rp[(f0+8)*BB + b0]     = acc[mt][nt2][2];
                rp[(f0+8)*BB + b0 + 1] = acc[mt][nt2][3];
            }
        }
    __syncthreads();
    for (int p = tid; p < FREQ*BB; p += 256) {
        float s = 0.0f;
#pragma unroll
        for (int w = 0; w < 8; w++) s += sm.red[w*(FREQ*BB) + p];
        g_gpart[(size_t)p*NCHUNK + chunk] = s;
    }
}

/* ---------------- gate: warp-per-p coalesced reduce + sigmoid ------------ */
__global__ void gate_kernel(const float* __restrict__ br) {
    int warp = threadIdx.x >> 5;
    int lane = threadIdx.x & 31;
    int p = blockIdx.x*8 + warp;           /* grid 160, p = f*32 + b */
    const float* gp = g_gpart + (size_t)p*NCHUNK;
    float s = 0.0f;
    for (int c = lane; c < NCHUNK; c += 32) s += gp[c];
#pragma unroll
    for (int o = 16; o > 0; o >>= 1)
        s += __shfl_xor_sync(0xffffffffu, s, o);
    if (lane == 0) {
        int f = p >> 5;
        int b = p & 31;
        s += __ldg(&br[f]);
        g_gates[b*FREQ + f] = 1.0f / (1.0f + expf(-s));
    }
}

/* ---------------- projection + fused wtd mean: grid (b, f), 128 thr ------ */
__global__ void proj_kernel(float* __restrict__ out, int out_size) {
    int b = blockIdx.x;
    int f = blockIdx.y;
    int tid  = threadIdx.x;
    int warp = tid >> 5;
    int lane = tid & 31;
    const float2* tp = g_trig + f*WW;
    float gate = g_gates[b*FREQ + f];
    for (int h = warp; h < HH; h += 4) {
        const float* xp = g_feats + ((size_t)b*HH + h)*WW;
        float s = 0.0f, c = 0.0f;
#pragma unroll
        for (int q = 0; q < 8; q++) {
            int w = lane + q*32;
            float v = xp[w];
            float2 tc = tp[w];
            s += tc.x*v;
            c += tc.y*v;
        }
#pragma unroll
        for (int o = 16; o > 0; o >>= 1) {
            s += __shfl_xor_sync(0xffffffffu, s, o);
            c += __shfl_xor_sync(0xffffffffu, c, o);
        }
        if (lane == 0) {
            s *= (1.0f/(float)WW);
            c *= (1.0f/(float)WW);
            out[(size_t)b*(FREQ*HH) + f*HH + h] = sqrtf(s*s + c*c) * gate;
        }
    }

    if (b == 0 && f == 0) {
        __shared__ float red[128];
        float s = 0.0f;
        for (int i = tid; i < BB*FREQ; i += 128) {
            int ff = i % FREQ;
            s += g_gates[i] * (2.0f * (float)(ff+1));
        }
        red[tid] = s;
        __syncthreads();
        for (int o = 64; o > 0; o >>= 1) {
            if (tid < o) red[tid] += red[tid + o];
            __syncthreads();
        }
        if (tid == 0) out[out_size - 1] = red[0] / (float)(BB*FREQ);
    }
}

/* ---------------- launch -------------------------------------------------- */
extern "C" void kernel_launch(void* const* d_in, const int* in_sizes, int n_in,
                              void* d_out, int out_size) {
    const float* in = (const float*)d_in[0];
    const float* w0 = (const float*)d_in[1];
    const float* b0 = (const float*)d_in[2];
    const float* w1 = (const float*)d_in[3];
    const float* b1 = (const float*)d_in[4];
    const float* wf = (const float*)d_in[5];
    const float* bf = (const float*)d_in[6];
    const float* wr = (const float*)d_in[7];
    const float* br = (const float*)d_in[8];
    float* out = (float*)d_out;

    cudaFuncSetAttribute(conv1_mega,
                         cudaFuncAttributeMaxDynamicSharedMemorySize, SM1);

    conv1_mega<<<148, 512, SM1>>>(in, w0, b0, w1, b1);
    fc_plus<<<1468, 256>>>(wr, in, wf, bf);
    gate_kernel<<<160, 256>>>(br);
    proj_kernel<<<dim3(BB, FREQ), 128>>>(out, out_size);
}

// round 17
// speedup vs baseline: 1.4684x; 1.4684x over previous
#include <cuda_runtime.h>
#include <cuda_bf16.h>
#include <math.h>
#include <stdint.h>

#define BB   32
#define HH   40
#define WW   256
#define FREQ 40
#define C0   32
#define H0   38
#define C1   64
#define H1   36
#define W1   252
#define K_FC (C1*H1*W1)          /* 580608 */
#define NCHUNK 148               /* fc blocks; 4536 k128-tiles split 31/30 */
#define TWO_PI 6.28318530717958647692f

/* ---------------- scratch (device globals) ------------------------------- */
__device__ __nv_bfloat16 g_x1h[(size_t)BB*K_FC];      /* conv1 out, bf16   */
__device__ float         g_feats[BB*HH*WW];
__device__ float         g_sin[FREQ*WW];
__device__ float         g_cos[FREQ*WW];
__device__ float         g_gpart[(size_t)FREQ*BB*NCHUNK];  /* [p][chunk] */
__device__ float         g_gates[BB*FREQ];

/* ---------------- helpers ------------------------------------------------- */
__device__ __forceinline__ uint32_t packbf2(float lo, float hi) {
    __nv_bfloat162 h = __floats2bfloat162_rn(lo, hi);
    return *(uint32_t*)&h;
}

__device__ __forceinline__ void mma_bf16(float c[4], const uint32_t a[4],
                                         const uint32_t b[2]) {
    asm volatile(
        "mma.sync.aligned.m16n8k16.row.col.f32.bf16.bf16.f32 "
        "{%0,%1,%2,%3}, {%4,%5,%6,%7}, {%8,%9}, {%0,%1,%2,%3};"
        : "+f"(c[0]), "+f"(c[1]), "+f"(c[2]), "+f"(c[3])
        : "r"(a[0]), "r"(a[1]), "r"(a[2]), "r"(a[3]), "r"(b[0]), "r"(b[1]));
}

/* ---------------- conv1_mega: conv0 fused, persistent, double-buffered ----
 * Grid 148 CTAs x 512 thr; tiles (i2, b), tile = bid + k*148, 576 total.
 * Per tile: conv0 (1->32ch 3x3 + bias + relu, bf16x2-packed) computed
 * straight into the smem A-slab [icp(16)][dr(4)][XR=258]; weights built
 * in-CTA once into wsm (uint4 frag order).  conv0 of tile k+1 overlaps
 * MMA of tile k (disjoint buffers, one sync pair per tile).
 * Warp = rsel(2) x nhalf(2) x mblk(4); 64j x 32oc tile, 16 MMA per k16. */
#define XR    258
#define BUFU  (64*XR)                       /* 16512 u32 */
#define SM1   ((2*BUFU + 2304*4)*4)         /* 168960 bytes */

__device__ __forceinline__ void conv0_tile(uint32_t* dst,
                                           const float* __restrict__ in,
                                           const float* __restrict__ w0,
                                           const float* __restrict__ b0,
                                           int tile, int tid) {
    int i2t = tile % 18, bt = tile / 18;
    const float* ip = in + (size_t)bt*HH*WW;
    for (int idx = tid; idx < 4096; idx += 512) {
        int jg = idx & 63;          /* 64 groups of 4 cols */
        int t2 = idx >> 6;
        int dr = t2 & 3;
        int op = t2 >> 2;           /* icp 0..15 */
        int j0 = jg*4;
        int oc0 = op*2;
        int ir  = 2*i2t + dr;       /* x0 row, <= 37 */

        float wA[9], wB[9];
#pragma unroll
        for (int q = 0; q < 9; q++) {
            wA[q] = __ldg(&w0[oc0*9+q]);
            wB[q] = __ldg(&w0[oc0*9+9+q]);
        }
        float biasA = __ldg(&b0[oc0]);
        float biasB = __ldg(&b0[oc0+1]);
        float aA[4] = {biasA, biasA, biasA, biasA};
        float aB[4] = {biasB, biasB, biasB, biasB};

#pragma unroll
        for (int di = 0; di < 3; di++) {
            const float* row = ip + (ir+di)*WW;
            float x[6];
#pragma unroll
            for (int c = 0; c < 6; c++) x[c] = (j0+c < WW) ? row[j0+c] : 0.0f;
#pragma unroll
            for (int dj = 0; dj < 3; dj++) {
                float wa = wA[di*3+dj], wb = wB[di*3+dj];
#pragma unroll
                for (int q = 0; q < 4; q++) {
                    aA[q] += wa * x[q+dj];
                    aB[q] += wb * x[q+dj];
                }
            }
        }
        uint32_t v[4];
#pragma unroll
        for (int q = 0; q < 4; q++) {
            bool ok = (j0+q < 254);
            v[q] = packbf2(ok ? fmaxf(aA[q], 0.0f) : 0.0f,
                           ok ? fmaxf(aB[q], 0.0f) : 0.0f);
        }
        uint32_t* o = dst + (op*4 + dr)*XR + j0;
        *(uint2*)(o)     = make_uint2(v[0], v[1]);
        *(uint2*)(o + 2) = make_uint2(v[2], v[3]);
    }
}

__global__ void __launch_bounds__(512)
conv1_mega(const float* __restrict__ in,
           const float* __restrict__ w0,
           const float* __restrict__ b0,
           const float* __restrict__ w1,
           const float* __restrict__ b1) {
    extern __shared__ uint32_t smem[];
    uint4* wsm = (uint4*)(smem + 2*BUFU);

    int tid = threadIdx.x;
    int bid = blockIdx.x;

    /* build conv1 weight fragments in-CTA ([t9][kh][nq][lane] -> uint4) */
    for (int t = tid; t < 2304; t += 512) {
        int lane = t & 31;
        int nq   = (t >> 5) & 3;
        int kh   = (t >> 7) & 1;
        int t9   = t >> 8;
        int gid = lane >> 2, tig = lane & 3;
        int ic0 = 2*tig + 16*kh;
        int oc0 = nq*16 + gid;
        int oc1 = oc0 + 8;
        uint4 v;
        v.x = packbf2(__ldg(&w1[oc0*288 + (ic0  )*9 + t9]),
                      __ldg(&w1[oc0*288 + (ic0+1)*9 + t9]));
        v.y = packbf2(__ldg(&w1[oc0*288 + (ic0+8)*9 + t9]),
                      __ldg(&w1[oc0*288 + (ic0+9)*9 + t9]));
        v.z = packbf2(__ldg(&w1[oc1*288 + (ic0  )*9 + t9]),
                      __ldg(&w1[oc1*288 + (ic0+1)*9 + t9]));
        v.w = packbf2(__ldg(&w1[oc1*288 + (ic0+8)*9 + t9]),
                      __ldg(&w1[oc1*288 + (ic0+9)*9 + t9]));
        wsm[t] = v;
    }
    /* zero pad cols 256..257 of both buffers */
    if (tid < 256) {
        int bsel = tid >> 7, rr = (tid >> 1) & 63, c = tid & 1;
        smem[bsel*BUFU + rr*XR + 256 + c] = 0u;
    }

    int ntiles = (bid < 132) ? 4 : 3;

    conv0_tile(smem, in, w0, b0, bid, tid);   /* tile 0 -> buf0 */
    __syncthreads();

    int warp  = tid >> 5;
    int lane  = tid & 31;
    int mblk  = warp & 3;
    int nhalf = (warp >> 2) & 1;
    int rsel  = warp >> 3;
    int gid   = lane >> 2;
    int tig   = lane & 3;

    for (int k = 0; k < ntiles; k++) {
        if (k + 1 < ntiles)
            conv0_tile(smem + ((k+1)&1)*BUFU, in, w0, b0, bid + (k+1)*148, tid);
        __syncthreads();

        const uint32_t* xsp = smem + (k&1)*BUFU;
        int tile = bid + k*148;
        int i2t = tile % 18, bt = tile / 18;

        float cacc[4][4][4];
#pragma unroll
        for (int mf = 0; mf < 4; mf++)
#pragma unroll
            for (int nf = 0; nf < 4; nf++)
#pragma unroll
                for (int q = 0; q < 4; q++) cacc[mf][nf][q] = 0.0f;

#pragma unroll
        for (int t9 = 0; t9 < 9; t9++) {
            int di = t9 / 3, dj = t9 % 3;
            int dr = di + rsel;
#pragma unroll
            for (int kh = 0; kh < 2; kh++) {
                uint4 wv0 = wsm[((t9*2 + kh)*4 + 2*nhalf    )*32 + lane];
                uint4 wv1 = wsm[((t9*2 + kh)*4 + 2*nhalf + 1)*32 + lane];
                uint32_t bfrag[4][2];
                bfrag[0][0] = wv0.x; bfrag[0][1] = wv0.y;
                bfrag[1][0] = wv0.z; bfrag[1][1] = wv0.w;
                bfrag[2][0] = wv1.x; bfrag[2][1] = wv1.y;
                bfrag[3][0] = wv1.z; bfrag[3][1] = wv1.w;
                const uint32_t* xa = xsp + ((kh*8 + tig    )*4 + dr)*XR + dj;
                const uint32_t* xb = xsp + ((kh*8 + tig + 4)*4 + dr)*XR + dj;
#pragma unroll
                for (int mf = 0; mf < 4; mf++) {
                    int j0 = mblk*64 + mf*16 + gid;
                    uint32_t afrag[4];
                    afrag[0] = xa[j0];
                    afrag[1] = xa[j0 + 8];
                    afrag[2] = xb[j0];
                    afrag[3] = xb[j0 + 8];
#pragma unroll
                    for (int nf = 0; nf < 4; nf++)
                        mma_bf16(cacc[mf][nf], afrag, bfrag[nf]);
                }
            }
        }

        /* epilogue: bias + relu + bf16 store to g_x1h[b][oc][i][j] */
        int i = 2*i2t + rsel;
#pragma unroll
        for (int nf = 0; nf < 4; nf++) {
            int oc = nhalf*32 + nf*8 + tig*2;
            float bias0 = __ldg(&b1[oc]);
            float bias1 = __ldg(&b1[oc+1]);
            __nv_bfloat16* o0 = g_x1h + (size_t)bt*K_FC +
                                (size_t)oc*(H1*W1) + (size_t)i*W1;
            __nv_bfloat16* o1 = o0 + H1*W1;
#pragma unroll
            for (int mf = 0; mf < 4; mf++) {
                int j = mblk*64 + mf*16 + gid;
                if (j < W1) {
                    o0[j] = __float2bfloat16_rn(fmaxf(cacc[mf][nf][0] + bias0, 0.0f));
                    o1[j] = __float2bfloat16_rn(fmaxf(cacc[mf][nf][1] + bias1, 0.0f));
                }
                if (j + 8 < W1) {
                    o0[j+8] = __float2bfloat16_rn(fmaxf(cacc[mf][nf][2] + bias0, 0.0f));
                    o1[j+8] = __float2bfloat16_rn(fmaxf(cacc[mf][nf][3] + bias1, 0.0f));
                }
            }
        }
        __syncthreads();
    }
}

/* ---------------- FC via bf16 tensor cores, register prefetch ------------
 * 148 blocks; 4536 k128-tiles split 31/30. */
__global__ void __launch_bounds__(256) fc_kernel(const float* __restrict__ wr) {
    __shared__ union {
        struct { uint32_t wrs[48*68]; uint32_t x1s[32*68]; } t;
        float red[8*FREQ*BB];
    } sm;
    int chunk = blockIdx.x;
    int tid   = threadIdx.x;
    int warp  = tid >> 5;
    int lane  = tid & 31;
    int gid   = lane >> 2;
    int tig   = lane & 3;

    int tile0 = chunk*30 + ((chunk < 96) ? chunk : 96);
    int nt    = 30 + ((chunk < 96) ? 1 : 0);

    for (int s = tid; s < 8*68; s += 256) sm.t.wrs[40*68 + s] = 0u;

    float acc[3][4][4];
#pragma unroll
    for (int mt = 0; mt < 3; mt++)
#pragma unroll
        for (int nt2 = 0; nt2 < 4; nt2++)
#pragma unroll
            for (int q = 0; q < 4; q++) acc[mt][nt2][q] = 0.0f;

    const float4* wr4 = (const float4*)wr;
    float4 wbuf[5];
    uint4  xbuf[2];

    {
        int k0 = tile0*128;
#pragma unroll
        for (int s = 0; s < 5; s++) {
            int idx = tid + s*256;
            int r = idx >> 5, cc = idx & 31;
            wbuf[s] = wr4[(size_t)r*(K_FC/4) + (k0 >> 2) + cc];
        }
#pragma unroll
        for (int s = 0; s < 2; s++) {
            int idx = tid + s*256;
            int r = idx >> 4, cc = idx & 15;
            xbuf[s] = *(const uint4*)(g_x1h + (size_t)r*K_FC + k0 + cc*8);
        }
    }

    for (int tile = 0; tile < nt; tile++) {
#pragma unroll
        for (int s = 0; s < 5; s++) {
            int idx = tid + s*256;
            int r = idx >> 5, cc = idx & 31;
            sm.t.wrs[r*68 + 2*cc]     = packbf2(wbuf[s].x, wbuf[s].y);
            sm.t.wrs[r*68 + 2*cc + 1] = packbf2(wbuf[s].z, wbuf[s].w);
        }
#pragma unroll
        for (int s = 0; s < 2; s++) {
            int idx = tid + s*256;
            int r = idx >> 4, cc = idx & 15;
            *(uint4*)&sm.t.x1s[r*68 + cc*4] = xbuf[s];
        }
        __syncthreads();

        if (tile + 1 < nt) {
            int k0 = (tile0 + tile + 1)*128;
#pragma unroll
            for (int s = 0; s < 5; s++) {
                int idx = tid + s*256;
                int r = idx >> 5, cc = idx & 31;
                wbuf[s] = wr4[(size_t)r*(K_FC/4) + (k0 >> 2) + cc];
            }
#pragma unroll
            for (int s = 0; s < 2; s++) {
                int idx = tid + s*256;
                int r = idx >> 4, cc = idx & 15;
                xbuf[s] = *(const uint4*)(g_x1h + (size_t)r*K_FC + k0 + cc*8);
            }
        }

        int ko = warp*8 + tig;
        uint32_t bfrag[4][2];
#pragma unroll
        for (int nt2 = 0; nt2 < 4; nt2++) {
            bfrag[nt2][0] = sm.t.x1s[(nt2*8 + gid)*68 + ko];
            bfrag[nt2][1] = sm.t.x1s[(nt2*8 + gid)*68 + ko + 4];
        }
#pragma unroll
        for (int mt = 0; mt < 3; mt++) {
            uint32_t afrag[4];
            afrag[0] = sm.t.wrs[(mt*16 + gid    )*68 + ko];
            afrag[1] = sm.t.wrs[(mt*16 + gid + 8)*68 + ko];
            afrag[2] = sm.t.wrs[(mt*16 + gid    )*68 + ko + 4];
            afrag[3] = sm.t.wrs[(mt*16 + gid + 8)*68 + ko + 4];
#pragma unroll
            for (int nt2 = 0; nt2 < 4; nt2++)
                mma_bf16(acc[mt][nt2], afrag, bfrag[nt2]);
        }
        __syncthreads();
    }

#pragma unroll
    for (int mt = 0; mt < 3; mt++)
#pragma unroll
        for (int nt2 = 0; nt2 < 4; nt2++) {
            int f0 = mt*16 + gid;
            int b0 = nt2*8 + 2*tig;
            float* rp = sm.red + warp*(FREQ*BB);
            if (f0 < FREQ) {
                rp[f0*BB + b0]     = acc[mt][nt2][0];
                rp[f0*BB + b0 + 1] = acc[mt][nt2][1];
            }
            if (f0 + 8 < FREQ) {
                rp[(f0+8)*BB + b0]     = acc[mt][nt2][2];
                rp[(f0+8)*BB + b0 + 1] = acc[mt][nt2][3];
            }
        }
    __syncthreads();
    for (int p = tid; p < FREQ*BB; p += 256) {
        float s = 0.0f;
#pragma unroll
        for (int w = 0; w < 8; w++) s += sm.red[w*(FREQ*BB) + p];
        g_gpart[(size_t)p*NCHUNK + chunk] = s;
    }
}

/* ---------------- gate + feats + trig fused ------------------------------
 * blocks [0,160): gate reduce+sigmoid; [160,1440): feats; [1440,1480): trig */
__global__ void gate_feats_kernel(const float* __restrict__ in,
                                  const float* __restrict__ wf,
                                  const float* __restrict__ bf,
                                  const float* __restrict__ br) {
    int bid = blockIdx.x;
    int tid = threadIdx.x;
    if (bid < 160) {
        int warp = tid >> 5;
        int lane = tid & 31;
        int p = bid*8 + warp;              /* p = f*32 + b */
        const float* gp = g_gpart + (size_t)p*NCHUNK;
        float s = 0.0f;
        for (int c = lane; c < NCHUNK; c += 32) s += gp[c];
#pragma unroll
        for (int o = 16; o > 0; o >>= 1)
            s += __shfl_xor_sync(0xffffffffu, s, o);
        if (lane == 0) {
            int f = p >> 5;
            int b = p & 31;
            s += __ldg(&br[f]);
            g_gates[b*FREQ + f] = 1.0f / (1.0f + expf(-s));
        }
    } else if (bid < 1440) {
        int idx = (bid - 160)*256 + tid;
        int w = idx & (WW-1);
        const float* row = in + (idx - w);
        float acc = __ldg(&bf[0]);
#pragma unroll
        for (int t = 0; t < 5; t++) {
            int ww = w + t - 2;
            if (ww >= 0 && ww < WW) acc += __ldg(&wf[t]) * row[ww];
        }
        g_feats[idx] = acc;
    } else {
        int f = bid - 1440;
        int w = tid;
        float fs = 2.0f * (float)(f+1);
        float t  = (0.5f/255.0f) * (float)w;
        float ph = TWO_PI * fs * t;
        float sv, cv;
        sincosf(ph, &sv, &cv);
        g_sin[f*WW + w] = sv;
        g_cos[f*WW + w] = cv;
    }
}

/* ---------------- projection + fused wtd mean: grid (b, f), 128 thr ------ */
__global__ void proj_kernel(float* __restrict__ out, int out_size) {
    int b = blockIdx.x;
    int f = blockIdx.y;
    int tid  = threadIdx.x;
    int warp = tid >> 5;
    int lane = tid & 31;
    const float* sp = g_sin + f*WW;
    const float* cp = g_cos + f*WW;
    float gate = g_gates[b*FREQ + f];
    for (int h = warp; h < HH; h += 4) {
        const float* xp = g_feats + ((size_t)b*HH + h)*WW;
        float s = 0.0f, c = 0.0f;
#pragma unroll
        for (int q = 0; q < 8; q++) {
            int w = lane + q*32;
            float v = xp[w];
            s += sp[w]*v;
            c += cp[w]*v;
        }
#pragma unroll
        for (int o = 16; o > 0; o >>= 1) {
            s += __shfl_xor_sync(0xffffffffu, s, o);
            c += __shfl_xor_sync(0xffffffffu, c, o);
        }
        if (lane == 0) {
            s *= (1.0f/(float)WW);
            c *= (1.0f/(float)WW);
            out[(size_t)b*(FREQ*HH) + f*HH + h] = sqrtf(s*s + c*c) * gate;
        }
    }

    if (b == 0 && f == 0) {
        __shared__ float red[128];
        float s = 0.0f;
        for (int i = tid; i < BB*FREQ; i += 128) {
            int ff = i % FREQ;
            s += g_gates[i] * (2.0f * (float)(ff+1));
        }
        red[tid] = s;
        __syncthreads();
        for (int o = 64; o > 0; o >>= 1) {
            if (tid < o) red[tid] += red[tid + o];
            __syncthreads();
        }
        if (tid == 0) out[out_size - 1] = red[0] / (float)(BB*FREQ);
    }
}

/* ---------------- launch -------------------------------------------------- */
extern "C" void kernel_launch(void* const* d_in, const int* in_sizes, int n_in,
                              void* d_out, int out_size) {
    const float* in = (const float*)d_in[0];
    const float* w0 = (const float*)d_in[1];
    const float* b0 = (const float*)d_in[2];
    const float* w1 = (const float*)d_in[3];
    const float* b1 = (const float*)d_in[4];
    const float* wf = (const float*)d_in[5];
    const float* bf = (const float*)d_in[6];
    const float* wr = (const float*)d_in[7];
    const float* br = (const float*)d_in[8];
    float* out = (float*)d_out;

    cudaFuncSetAttribute(conv1_mega,
                         cudaFuncAttributeMaxDynamicSharedMemorySize, SM1);

    conv1_mega<<<148, 512, SM1>>>(in, w0, b0, w1, b1);
    fc_kernel<<<NCHUNK, 256>>>(wr);
    gate_feats_kernel<<<1480, 256>>>(in, wf, bf, br);
    proj_kernel<<<dim3(BB, FREQ), 128>>>(out, out_size);
}